// round 1
// baseline (speedup 1.0000x reference)
#include <cuda_runtime.h>
#include <math.h>

#define NL    2048
#define MODES 4096
#define APL   8

// Scratch (allocation-free, __device__ globals per harness rules)
__device__ float g_x3[NL];
__device__ float g_h[MODES];

// Stable real part of complex tanh(x * (Sr + i*Si)) for real x.
// Re tanh(a+ib) = sinh(2a) / (cosh(2a) + cos(2b))
//              = sign(a)*(1 - e^{-4|a|}) / (1 + e^{-4|a|} + 2 cos(2b) e^{-2|a|})
__device__ __forceinline__ double re_tanh_cmul(double x, double Sr, double Si) {
    double a = x * Sr;
    double b = x * Si;
    double aa = fabs(a);
    double e2 = exp(-2.0 * aa);
    double e4 = e2 * e2;
    double num = 1.0 - e4;
    if (a < 0.0) num = -num;
    double den = 1.0 + e4 + 2.0 * cos(2.0 * b) * e2;
    return num / den;
}

// Stage 1: compute S0,S1,S2 = sums of the complex w_fft vectors, then the
// 3-stage scalar tanh chain on model_p[:,0]. Single block.
__global__ void stage1_kernel(const float* __restrict__ model_p,
                              const float* __restrict__ w0,
                              const float* __restrict__ w1,
                              const float* __restrict__ w2) {
    __shared__ double sred[256];
    __shared__ double S[6];
    const int t = threadIdx.x;
    const float* ws[3] = {w0, w1, w2};

    for (int k = 0; k < 3; k++) {
        double sr = 0.0, si = 0.0;
        for (int i = t; i < MODES; i += 256) {
            sr += (double)ws[k][2 * i];        // interleaved complex64: re
            si += (double)ws[k][2 * i + 1];    // im
        }
        sred[t] = sr; __syncthreads();
        for (int o = 128; o > 0; o >>= 1) { if (t < o) sred[t] += sred[t + o]; __syncthreads(); }
        if (t == 0) S[2 * k] = sred[0];
        __syncthreads();
        sred[t] = si; __syncthreads();
        for (int o = 128; o > 0; o >>= 1) { if (t < o) sred[t] += sred[t + o]; __syncthreads(); }
        if (t == 0) S[2 * k + 1] = sred[0];
        __syncthreads();
    }

    const double S0r = S[0], S0i = S[1];
    const double S1r = S[2], S1i = S[3];
    const double S2r = S[4], S2i = S[5];

    for (int f = t; f < NL; f += 256) {
        double x = (double)model_p[(size_t)f * MODES];   // only column 0 matters
        x = re_tanh_cmul(x, S0r, S0i);
        x = re_tanh_cmul(x, S1r, S1i);
        x = re_tanh_cmul(x, S2r, S2i);
        g_x3[f] = (float)x;
    }
}

// Warp-per-row matvec: out[row] = act(dot(W[row,:], v) + bias[row]).
// W row-major [ROWS, COLS], COLS multiple of 128, float4 vectorized.
template <int COLS, bool TANH, bool SRC_X3>
__global__ void matvec_kernel(const float* __restrict__ W,
                              const float* __restrict__ bias,
                              float* __restrict__ out,
                              int rows) {
    const int warp = (blockIdx.x * blockDim.x + threadIdx.x) >> 5;
    const int lane = threadIdx.x & 31;
    if (warp >= rows) return;

    const float* v = SRC_X3 ? g_x3 : g_h;
    const float4* __restrict__ row = reinterpret_cast<const float4*>(W + (size_t)warp * COLS);
    const float4* __restrict__ v4  = reinterpret_cast<const float4*>(v);

    float acc = 0.0f;
    #pragma unroll 4
    for (int i = lane; i < COLS / 4; i += 32) {
        float4 w = row[i];
        float4 x = __ldg(&v4[i]);
        acc += w.x * x.x + w.y * x.y + w.z * x.z + w.w * x.w;
    }
    #pragma unroll
    for (int o = 16; o > 0; o >>= 1)
        acc += __shfl_xor_sync(0xffffffffu, acc, o);

    if (lane == 0) {
        float r = acc + bias[warp];
        if (TANH) r = tanhf(r);
        if (SRC_X3) g_h[warp] = r;   // stage-2 output lives in scratch
        else        out[warp] = r;
    }
}

extern "C" void kernel_launch(void* const* d_in, const int* in_sizes, int n_in,
                              void* d_out, int out_size) {
    // metadata order: model_p, w_fft_0, w_fft_1, w_fft_2, lin1_w, lin1_b, lin2_w, lin2_b
    const float* model_p = (const float*)d_in[0];
    const float* w0      = (const float*)d_in[1];   // complex64 interleaved
    const float* w1      = (const float*)d_in[2];
    const float* w2      = (const float*)d_in[3];
    const float* lin1_w  = (const float*)d_in[4];   // (4096, 2048)
    const float* lin1_b  = (const float*)d_in[5];   // (4096,)
    const float* lin2_w  = (const float*)d_in[6];   // (16384, 4096)
    const float* lin2_b  = (const float*)d_in[7];   // (16384,)
    float* out = (float*)d_out;                     // 16384

    (void)in_sizes; (void)n_in; (void)out_size;

    stage1_kernel<<<1, 256>>>(model_p, w0, w1, w2);

    // h = tanh(lin1_w @ x3 + lin1_b): 4096 rows x 2048 cols, warp per row
    matvec_kernel<NL, true, true><<<(MODES * 32) / 256, 256>>>(lin1_w, lin1_b, out, MODES);

    // out = lin2_w @ h + lin2_b: 16384 rows x 4096 cols, warp per row
    matvec_kernel<MODES, false, false><<<(NL * APL * 32) / 256, 256>>>(lin2_w, lin2_b, out, NL * APL);
}

// round 2
// speedup vs baseline: 2.0773x; 2.0773x over previous
#include <cuda_runtime.h>
#include <math.h>

#define NL    2048
#define MODES 4096
#define APL   8

// Scratch (allocation-free, __device__ globals per harness rules)
__device__ float g_x3[NL];
__device__ float g_h[MODES];

// Stable real part of complex tanh(x * (Sr + i*Si)) for real x.
// Re tanh(a+ib) = sinh(2a) / (cosh(2a) + cos(2b))
//              = sign(a)*(1 - e^{-4|a|}) / (1 + e^{-4|a|} + 2 cos(2b) e^{-2|a|})
__device__ __forceinline__ double re_tanh_cmul(double x, double Sr, double Si) {
    double a = x * Sr;
    double b = x * Si;
    double aa = fabs(a);
    double e2 = exp(-2.0 * aa);
    double e4 = e2 * e2;
    double num = 1.0 - e4;
    if (a < 0.0) num = -num;
    double den = 1.0 + e4 + 2.0 * cos(2.0 * b) * e2;
    return num / den;
}

// Stage 1: 16 blocks x 128 threads. Each block redundantly computes
// S_k = sum(w_fft_k) (cheap, L2-resident), then each thread runs the
// 3-stage scalar complex-tanh chain for exactly one layer element.
__global__ void stage1_kernel(const float* __restrict__ model_p,
                              const float* __restrict__ w0,
                              const float* __restrict__ w1,
                              const float* __restrict__ w2) {
    const int t    = threadIdx.x;   // 0..127
    const int lane = t & 31;
    const int warp = t >> 5;        // 0..3

    __shared__ double Ssh[6];
    __shared__ double red[6][4];

    const float* ws[3] = {w0, w1, w2};

    // Each warp handles reductions; all 4 warps cooperate on each k.
    for (int k = 0; k < 3; k++) {
        double sr = 0.0, si = 0.0;
        // interleaved complex64; 4096 complex elems, 128 threads -> 32 each
        const float2* wk = reinterpret_cast<const float2*>(ws[k]);
        for (int i = t; i < MODES; i += 128) {
            float2 c = __ldg(&wk[i]);
            sr += (double)c.x;
            si += (double)c.y;
        }
        #pragma unroll
        for (int o = 16; o > 0; o >>= 1) {
            sr += __shfl_xor_sync(0xffffffffu, sr, o);
            si += __shfl_xor_sync(0xffffffffu, si, o);
        }
        if (lane == 0) { red[2 * k][warp] = sr; red[2 * k + 1][warp] = si; }
    }
    __syncthreads();
    if (t < 6) Ssh[t] = red[t][0] + red[t][1] + red[t][2] + red[t][3];
    __syncthreads();

    const double S0r = Ssh[0], S0i = Ssh[1];
    const double S1r = Ssh[2], S1i = Ssh[3];
    const double S2r = Ssh[4], S2i = Ssh[5];

    const int f = blockIdx.x * 128 + t;   // 16 blocks * 128 = 2048 = NL
    double x = (double)__ldg(&model_p[(size_t)f * MODES]);  // only column 0 matters
    x = re_tanh_cmul(x, S0r, S0i);
    x = re_tanh_cmul(x, S1r, S1i);
    x = re_tanh_cmul(x, S2r, S2i);
    g_x3[f] = (float)x;
}

// Warp-per-row matvec: out[row] = act(dot(W[row,:], v) + bias[row]).
// W row-major [ROWS, COLS], COLS multiple of 128, float4 vectorized.
template <int COLS, bool TANH, bool SRC_X3>
__global__ void matvec_kernel(const float* __restrict__ W,
                              const float* __restrict__ bias,
                              float* __restrict__ out,
                              int rows) {
    const int warp = (blockIdx.x * blockDim.x + threadIdx.x) >> 5;
    const int lane = threadIdx.x & 31;
    if (warp >= rows) return;

    const float* v = SRC_X3 ? g_x3 : g_h;
    const float4* __restrict__ row = reinterpret_cast<const float4*>(W + (size_t)warp * COLS);
    const float4* __restrict__ v4  = reinterpret_cast<const float4*>(v);

    float acc = 0.0f;
    #pragma unroll 8
    for (int i = lane; i < COLS / 4; i += 32) {
        float4 w = row[i];
        float4 x = __ldg(&v4[i]);
        acc += w.x * x.x + w.y * x.y + w.z * x.z + w.w * x.w;
    }
    #pragma unroll
    for (int o = 16; o > 0; o >>= 1)
        acc += __shfl_xor_sync(0xffffffffu, acc, o);

    if (lane == 0) {
        float r = acc + bias[warp];
        if (TANH) r = tanhf(r);
        if (SRC_X3) g_h[warp] = r;   // stage-2 output lives in scratch
        else        out[warp] = r;
    }
}

extern "C" void kernel_launch(void* const* d_in, const int* in_sizes, int n_in,
                              void* d_out, int out_size) {
    // metadata order: model_p, w_fft_0, w_fft_1, w_fft_2, lin1_w, lin1_b, lin2_w, lin2_b
    const float* model_p = (const float*)d_in[0];
    const float* w0      = (const float*)d_in[1];   // complex64 interleaved
    const float* w1      = (const float*)d_in[2];
    const float* w2      = (const float*)d_in[3];
    const float* lin1_w  = (const float*)d_in[4];   // (4096, 2048)
    const float* lin1_b  = (const float*)d_in[5];   // (4096,)
    const float* lin2_w  = (const float*)d_in[6];   // (16384, 4096)
    const float* lin2_b  = (const float*)d_in[7];   // (16384,)
    float* out = (float*)d_out;                     // 16384

    (void)in_sizes; (void)n_in; (void)out_size;

    stage1_kernel<<<NL / 128, 128>>>(model_p, w0, w1, w2);

    // h = tanh(lin1_w @ x3 + lin1_b): 4096 rows x 2048 cols, warp per row
    matvec_kernel<NL, true, true><<<(MODES * 32) / 256, 256>>>(lin1_w, lin1_b, out, MODES);

    // out = lin2_w @ h + lin2_b: 16384 rows x 4096 cols, warp per row
    matvec_kernel<MODES, false, false><<<(NL * APL * 32) / 256, 256>>>(lin2_w, lin2_b, out, NL * APL);
}

// round 3
// speedup vs baseline: 2.3523x; 1.1324x over previous
#include <cuda_runtime.h>
#include <math.h>

#define NL    2048
#define MODES 4096
#define APL   8

// Scratch (allocation-free, __device__ globals per harness rules)
__device__ float g_x3[NL];
__device__ float g_h[MODES];

// Stable real part of complex tanh(x * (Sr + i*Si)) for real x, in float.
// Re tanh(a+ib) = sign(a)*(1 - e^{-4|a|}) / (1 + e^{-4|a|} + 2 cos(2b) e^{-2|a|})
// Safe in float here because a,b are proportional to x with coefficients of
// similar magnitude (~2048 each): when |a| is large, e^{-2|a|} kills the cos
// term before cosf's argument-reduction error matters; when |a| is small, |b|
// is small too and cosf is accurate.
__device__ __forceinline__ float re_tanh_cmul_f(float x, float Sr, float Si) {
    float a = x * Sr;
    float b = x * Si;
    float aa = fabsf(a);
    float e2 = __expf(-2.0f * aa);     // arg <= 0, high relative accuracy
    float e4 = e2 * e2;
    float num = 1.0f - e4;
    if (a < 0.0f) num = -num;
    float den = 1.0f + e4 + 2.0f * cosf(2.0f * b) * e2;
    return num / den;
}

// Stage 1: 16 blocks x 128 threads. Each block redundantly computes
// S_k = sum(w_fft_k) (L2-resident, cheap; accumulate in double, adds only),
// then each thread runs the 3-stage float complex-tanh chain for one layer.
__global__ void stage1_kernel(const float* __restrict__ model_p,
                              const float* __restrict__ w0,
                              const float* __restrict__ w1,
                              const float* __restrict__ w2) {
    const int t    = threadIdx.x;   // 0..127
    const int lane = t & 31;
    const int warp = t >> 5;        // 0..3

    __shared__ double Ssh[6];
    __shared__ double red[6][4];

    const float* ws[3] = {w0, w1, w2};

    for (int k = 0; k < 3; k++) {
        double sr0 = 0.0, si0 = 0.0, sr1 = 0.0, si1 = 0.0;
        const float2* wk = reinterpret_cast<const float2*>(ws[k]);
        // 4096 complex elems, 128 threads -> 32 each; 2 accumulators to break deps
        for (int i = t; i < MODES; i += 256) {
            float2 c0 = __ldg(&wk[i]);
            float2 c1 = __ldg(&wk[i + 128]);
            sr0 += (double)c0.x; si0 += (double)c0.y;
            sr1 += (double)c1.x; si1 += (double)c1.y;
        }
        double sr = sr0 + sr1, si = si0 + si1;
        #pragma unroll
        for (int o = 16; o > 0; o >>= 1) {
            sr += __shfl_xor_sync(0xffffffffu, sr, o);
            si += __shfl_xor_sync(0xffffffffu, si, o);
        }
        if (lane == 0) { red[2 * k][warp] = sr; red[2 * k + 1][warp] = si; }
    }
    __syncthreads();
    if (t < 6) Ssh[t] = red[t][0] + red[t][1] + red[t][2] + red[t][3];
    __syncthreads();

    const float S0r = (float)Ssh[0], S0i = (float)Ssh[1];
    const float S1r = (float)Ssh[2], S1i = (float)Ssh[3];
    const float S2r = (float)Ssh[4], S2i = (float)Ssh[5];

    const int f = blockIdx.x * 128 + t;   // 16 blocks * 128 = 2048 = NL
    float x = __ldg(&model_p[(size_t)f * MODES]);  // only column 0 matters
    x = re_tanh_cmul_f(x, S0r, S0i);
    x = re_tanh_cmul_f(x, S1r, S1i);
    x = re_tanh_cmul_f(x, S2r, S2i);
    g_x3[f] = x;
}

// Warp-per-row matvec: out[row] = act(dot(W[row,:], v) + bias[row]).
// W row-major [ROWS, COLS]. Each lane loads 2 float4s per iteration
// (both coalesced across the warp) to raise memory-level parallelism.
template <int COLS, bool TANH, bool SRC_X3>
__global__ void matvec_kernel(const float* __restrict__ W,
                              const float* __restrict__ bias,
                              float* __restrict__ out,
                              int rows) {
    const int warp = (blockIdx.x * blockDim.x + threadIdx.x) >> 5;
    const int lane = threadIdx.x & 31;
    if (warp >= rows) return;

    const float* v = SRC_X3 ? g_x3 : g_h;
    const float4* __restrict__ row = reinterpret_cast<const float4*>(W + (size_t)warp * COLS);
    const float4* __restrict__ v4  = reinterpret_cast<const float4*>(v);

    constexpr int N4 = COLS / 4;   // float4 count per row (512 or 1024)
    float acc0 = 0.0f, acc1 = 0.0f;
    #pragma unroll 4
    for (int base = 0; base < N4; base += 64) {
        int i0 = base + lane;
        int i1 = i0 + 32;
        float4 w0 = row[i0];
        float4 w1 = row[i1];
        float4 x0 = __ldg(&v4[i0]);
        float4 x1 = __ldg(&v4[i1]);
        acc0 += w0.x * x0.x + w0.y * x0.y + w0.z * x0.z + w0.w * x0.w;
        acc1 += w1.x * x1.x + w1.y * x1.y + w1.z * x1.z + w1.w * x1.w;
    }
    float acc = acc0 + acc1;
    #pragma unroll
    for (int o = 16; o > 0; o >>= 1)
        acc += __shfl_xor_sync(0xffffffffu, acc, o);

    if (lane == 0) {
        float r = acc + bias[warp];
        if (TANH) r = tanhf(r);
        if (SRC_X3) g_h[warp] = r;   // stage-2 output lives in scratch
        else        out[warp] = r;
    }
}

extern "C" void kernel_launch(void* const* d_in, const int* in_sizes, int n_in,
                              void* d_out, int out_size) {
    // metadata order: model_p, w_fft_0, w_fft_1, w_fft_2, lin1_w, lin1_b, lin2_w, lin2_b
    const float* model_p = (const float*)d_in[0];
    const float* w0      = (const float*)d_in[1];   // complex64 interleaved
    const float* w1      = (const float*)d_in[2];
    const float* w2      = (const float*)d_in[3];
    const float* lin1_w  = (const float*)d_in[4];   // (4096, 2048)
    const float* lin1_b  = (const float*)d_in[5];   // (4096,)
    const float* lin2_w  = (const float*)d_in[6];   // (16384, 4096)
    const float* lin2_b  = (const float*)d_in[7];   // (16384,)
    float* out = (float*)d_out;                     // 16384

    (void)in_sizes; (void)n_in; (void)out_size;

    stage1_kernel<<<NL / 128, 128>>>(model_p, w0, w1, w2);

    // h = tanh(lin1_w @ x3 + lin1_b): 4096 rows x 2048 cols, warp per row
    matvec_kernel<NL, true, true><<<(MODES * 32) / 256, 256>>>(lin1_w, lin1_b, out, MODES);

    // out = lin2_w @ h + lin2_b: 16384 rows x 4096 cols, warp per row
    matvec_kernel<MODES, false, false><<<(NL * APL * 32) / 256, 256>>>(lin2_w, lin2_b, out, NL * APL);
}

// round 4
// speedup vs baseline: 3.0055x; 1.2777x over previous
#include <cuda_runtime.h>
#include <math.h>

#define NL    2048
#define MODES 4096
#define APL   8

// Scratch (allocation-free, __device__ globals per harness rules)
__device__ float g_x3[NL];
__device__ float g_h[MODES];

// Stable real part of complex tanh(x * (Sr + i*Si)) for real x, in float.
// Re tanh(a+ib) = sign(a)*(1 - e^{-4|a|}) / (1 + e^{-4|a|} + 2 cos(2b) e^{-2|a|})
// Safe in float: a,b scale together (Sr≈Si≈2048), so the cos term only
// matters where |b| is small and cosf is accurate; den bounded away from 0.
__device__ __forceinline__ float re_tanh_cmul_f(float x, float Sr, float Si) {
    float a = x * Sr;
    float b = x * Si;
    float aa = fabsf(a);
    float e2 = __expf(-2.0f * aa);     // arg <= 0, high relative accuracy
    float e4 = e2 * e2;
    float num = 1.0f - e4;
    if (a < 0.0f) num = -num;
    float den = 1.0f + e4 + 2.0f * cosf(2.0f * b) * e2;
    return num / den;
}

// Stage 1: 16 blocks x 128 threads, all-FP32. Each block redundantly computes
// S_k = sum(w_fft_k) with float accumulators (per-acc magnitude <=8, error
// negligible vs S~2048), then each thread runs the 3-stage chain for one layer.
__global__ void stage1_kernel(const float* __restrict__ model_p,
                              const float* __restrict__ w0,
                              const float* __restrict__ w1,
                              const float* __restrict__ w2) {
    const int t    = threadIdx.x;   // 0..127
    const int lane = t & 31;
    const int warp = t >> 5;        // 0..3

    __shared__ float Ssh[6];
    __shared__ float red[6][4];

    const float* ws[3] = {w0, w1, w2};

    #pragma unroll
    for (int k = 0; k < 3; k++) {
        float sr0 = 0.f, si0 = 0.f, sr1 = 0.f, si1 = 0.f;
        const float4* wk = reinterpret_cast<const float4*>(ws[k]);  // 2 complex per float4
        // 2048 float4s, 128 threads -> 16 each; 2 streams for MLP
        #pragma unroll 4
        for (int i = t; i < MODES / 2; i += 256) {
            float4 c0 = __ldg(&wk[i]);
            float4 c1 = __ldg(&wk[i + 128]);
            sr0 += c0.x + c0.z;  si0 += c0.y + c0.w;
            sr1 += c1.x + c1.z;  si1 += c1.y + c1.w;
        }
        float sr = sr0 + sr1, si = si0 + si1;
        #pragma unroll
        for (int o = 16; o > 0; o >>= 1) {
            sr += __shfl_xor_sync(0xffffffffu, sr, o);
            si += __shfl_xor_sync(0xffffffffu, si, o);
        }
        if (lane == 0) { red[2 * k][warp] = sr; red[2 * k + 1][warp] = si; }
    }
    __syncthreads();
    if (t < 6) Ssh[t] = red[t][0] + red[t][1] + red[t][2] + red[t][3];
    __syncthreads();

    const float S0r = Ssh[0], S0i = Ssh[1];
    const float S1r = Ssh[2], S1i = Ssh[3];
    const float S2r = Ssh[4], S2i = Ssh[5];

    const int f = blockIdx.x * 128 + t;   // 16 blocks * 128 = 2048 = NL
    float x = __ldg(&model_p[(size_t)f * MODES]);  // only column 0 matters
    x = re_tanh_cmul_f(x, S0r, S0i);
    x = re_tanh_cmul_f(x, S1r, S1i);
    x = re_tanh_cmul_f(x, S2r, S2i);
    g_x3[f] = x;
}

// Warp-per-row matvec: out[row] = act(dot(W[row,:], v) + bias[row]).
// W row-major [ROWS, COLS]. 4 independent float4 streams per lane for MLP.
template <int COLS, bool TANH, bool SRC_X3>
__global__ void matvec_kernel(const float* __restrict__ W,
                              const float* __restrict__ bias,
                              float* __restrict__ out,
                              int rows) {
    const int warp = (blockIdx.x * blockDim.x + threadIdx.x) >> 5;
    const int lane = threadIdx.x & 31;
    if (warp >= rows) return;

    const float* v = SRC_X3 ? g_x3 : g_h;
    const float4* __restrict__ row = reinterpret_cast<const float4*>(W + (size_t)warp * COLS);
    const float4* __restrict__ v4  = reinterpret_cast<const float4*>(v);

    constexpr int N4 = COLS / 4;   // 512 (lin1) or 1024 (lin2)
    float acc0 = 0.0f, acc1 = 0.0f, acc2 = 0.0f, acc3 = 0.0f;
    #pragma unroll
    for (int base = 0; base < N4; base += 128) {
        int i0 = base + lane;
        float4 w0 = row[i0];
        float4 w1 = row[i0 + 32];
        float4 w2 = row[i0 + 64];
        float4 w3 = row[i0 + 96];
        float4 x0 = __ldg(&v4[i0]);
        float4 x1 = __ldg(&v4[i0 + 32]);
        float4 x2 = __ldg(&v4[i0 + 64]);
        float4 x3 = __ldg(&v4[i0 + 96]);
        acc0 += w0.x * x0.x + w0.y * x0.y + w0.z * x0.z + w0.w * x0.w;
        acc1 += w1.x * x1.x + w1.y * x1.y + w1.z * x1.z + w1.w * x1.w;
        acc2 += w2.x * x2.x + w2.y * x2.y + w2.z * x2.z + w2.w * x2.w;
        acc3 += w3.x * x3.x + w3.y * x3.y + w3.z * x3.z + w3.w * x3.w;
    }
    float acc = (acc0 + acc1) + (acc2 + acc3);
    #pragma unroll
    for (int o = 16; o > 0; o >>= 1)
        acc += __shfl_xor_sync(0xffffffffu, acc, o);

    if (lane == 0) {
        float r = acc + bias[warp];
        if (TANH) r = tanhf(r);
        if (SRC_X3) g_h[warp] = r;   // stage-2 output lives in scratch
        else        out[warp] = r;
    }
}

extern "C" void kernel_launch(void* const* d_in, const int* in_sizes, int n_in,
                              void* d_out, int out_size) {
    // metadata order: model_p, w_fft_0, w_fft_1, w_fft_2, lin1_w, lin1_b, lin2_w, lin2_b
    const float* model_p = (const float*)d_in[0];
    const float* w0      = (const float*)d_in[1];   // complex64 interleaved
    const float* w1      = (const float*)d_in[2];
    const float* w2      = (const float*)d_in[3];
    const float* lin1_w  = (const float*)d_in[4];   // (4096, 2048)
    const float* lin1_b  = (const float*)d_in[5];   // (4096,)
    const float* lin2_w  = (const float*)d_in[6];   // (16384, 4096)
    const float* lin2_b  = (const float*)d_in[7];   // (16384,)
    float* out = (float*)d_out;                     // 16384

    (void)in_sizes; (void)n_in; (void)out_size;

    stage1_kernel<<<NL / 128, 128>>>(model_p, w0, w1, w2);

    // h = tanh(lin1_w @ x3 + lin1_b): 4096 rows x 2048 cols, warp per row
    matvec_kernel<NL, true, true><<<(MODES * 32) / 256, 256>>>(lin1_w, lin1_b, out, MODES);

    // out = lin2_w @ h + lin2_b: 16384 rows x 4096 cols, warp per row
    matvec_kernel<MODES, false, false><<<(NL * APL * 32) / 256, 256>>>(lin2_w, lin2_b, out, NL * APL);
}